// round 15
// baseline (speedup 1.0000x reference)
#include <cuda_runtime.h>

#define NN 1024
#define NMASK 1023
#define NH 512
#define TC 32          // subband cols per block
#define TR 32          // subband rows per block
#define HROWS 70       // halo rows: 2*32 + 6
#define TSTRIDE 72     // intermediate row stride in floats

// lo[j] = w[7-j] (index reversal, free); hi[j] = (j odd) ? w[j] : -w[j]
// (negation folded into the FFMA operand modifier, free in SASS).
#define FMA_LO(v, j, s) (s) = fmaf((v), w[7 - (j)], (s))
#define FMA_HI(v, j, s) (s) = ((j) & 1) ? fmaf((v), w[(j)], (s)) \
                                        : fmaf((v), -w[(j)], (s))

__global__ __launch_bounds__(256, 6)
void wav2d_kernel(const float* __restrict__ x,
                  const float* __restrict__ bmt,
                  float* __restrict__ out)
{
    __shared__ float tmp[HROWS * TSTRIDE];   // 20160 B

    const int tid = threadIdx.x;
    const int b  = blockIdx.z;
    const int r0 = blockIdx.y * TR;
    const int c0 = blockIdx.x * TC;

    float w[8];
    #pragma unroll
    for (int j = 0; j < 8; ++j) w[j] = __ldg(&bmt[j]);

    const float* xb = x + (size_t)b * NN * NN;
    const int gr0  = 2 * r0 - 3;   // first halo row (wrapped)
    const int gc0a = 2 * c0 - 4;   // first halo col, 16B-aligned when in-bounds

    // ---- Phase 1: horizontal filter ----
    // Half-warp owns one tile row; lane hl owns float4 #hl of that row.
    // Interior-x path: 1 coalesced LDG.128/lane + 2-lane halo load; overlap
    // vectors obtained via width-16 shuffles (XU pipe) instead of extra LDG.
    const int  hl      = tid & 15;          // pair index / f4 index in row
    const int  rowbase = tid >> 4;          // 0..15
    const bool xint = (blockIdx.x >= 1) & (blockIdx.x <= 14);

    #pragma unroll
    for (int it = 0; it < 5; ++it) {
        int row = rowbase + 16 * it;
        if (row < HROWS) {
            int gr = (gr0 + row) & NMASK;
            const float* rowp = xb + (size_t)gr * NN;

            float f[12];
            if (xint) {
                const float4* rowp4 = (const float4*)(rowp + gc0a);
                float4 own = __ldg(rowp4 + hl);                 // f4 hl  = f[4hl..4hl+3]
                float4 gx = make_float4(0.f, 0.f, 0.f, 0.f);
                if (hl < 2) gx = __ldg(rowp4 + 16 + hl);        // halo f4 16,17

                const unsigned m = 0xffffffffu;
                float4 n1, n2;
                n1.x = __shfl_down_sync(m, own.x, 1, 16);
                n1.y = __shfl_down_sync(m, own.y, 1, 16);
                n1.z = __shfl_down_sync(m, own.z, 1, 16);
                n1.w = __shfl_down_sync(m, own.w, 1, 16);
                n2.x = __shfl_down_sync(m, own.x, 2, 16);
                n2.y = __shfl_down_sync(m, own.y, 2, 16);
                n2.z = __shfl_down_sync(m, own.z, 2, 16);
                float g0x = __shfl_sync(m, gx.x, 0, 16);
                float g0y = __shfl_sync(m, gx.y, 0, 16);
                float g0z = __shfl_sync(m, gx.z, 0, 16);
                float g0w = __shfl_sync(m, gx.w, 0, 16);
                float g1x = __shfl_sync(m, gx.x, 1, 16);
                float g1y = __shfl_sync(m, gx.y, 1, 16);
                float g1z = __shfl_sync(m, gx.z, 1, 16);

                if (hl == 15) {                 // n1 = f4(16), n2 = f4(17)
                    n1.x = g0x; n1.y = g0y; n1.z = g0z; n1.w = g0w;
                    n2.x = g1x; n2.y = g1y; n2.z = g1z;
                } else if (hl == 14) {          // n2 = f4(16)
                    n2.x = g0x; n2.y = g0y; n2.z = g0z;
                }

                f[0]=own.x; f[1]=own.y; f[2]=own.z;  f[3]=own.w;
                f[4]=n1.x;  f[5]=n1.y;  f[6]=n1.z;   f[7]=n1.w;
                f[8]=n2.x;  f[9]=n2.y;  f[10]=n2.z;  f[11]=0.f;   // f[11] unused
            } else {
                int base = gc0a + 4 * hl;
                #pragma unroll
                for (int j = 0; j < 12; ++j)
                    f[j] = __ldg(&rowp[(base + j) & NMASK]);
            }

            float sA0 = 0.f, sD0 = 0.f, sA1 = 0.f, sD1 = 0.f;
            #pragma unroll
            for (int j = 0; j < 8; ++j) {
                FMA_LO(f[1 + j], j, sA0);  FMA_HI(f[1 + j], j, sD0);
                FMA_LO(f[3 + j], j, sA1);  FMA_HI(f[3 + j], j, sD1);
            }
            *(float2*)&tmp[row * TSTRIDE + 2 * hl]      = make_float2(sA0, sA1);
            *(float2*)&tmp[row * TSTRIDE + 32 + 2 * hl] = make_float2(sD0, sD1);
        }
    }
    __syncthreads();

    // ---- Phase 2: vertical filter, warp-uniform; 8 output rows/thread ----
    // warp g: arr = g&1 (A cols [0,32) or D cols [32,64)), q = g>>1 (0..3).
    // Output rows 8q..8q+7 need tmp rows 16q..16q+21 (sliding window of 22).
    {
        const int tx  = tid & 31;
        const int g   = tid >> 5;
        const int arr = g & 1;
        const int q   = g >> 1;

        float sL[8] = {0,0,0,0,0,0,0,0};
        float sH[8] = {0,0,0,0,0,0,0,0};

        const float* col = &tmp[(16 * q) * TSTRIDE + 32 * arr + tx];
        #pragma unroll
        for (int i = 0; i < 22; ++i) {
            float v = col[i * TSTRIDE];
            #pragma unroll
            for (int m = 0; m < 8; ++m) {
                int j = i - 2 * m;
                if (j >= 0 && j < 8) {
                    FMA_LO(v, j, sL[m]);
                    FMA_HI(v, j, sH[m]);
                }
            }
        }

        // arr=0 -> top half rows; arr=1 -> bottom half (+NH).
        // Vertical low-pass -> left cols; high-pass -> right cols (+NH).
        float* ob = out + (size_t)b * NN * NN + (size_t)(arr * NH) * NN;
        const int C = c0 + tx;
        #pragma unroll
        for (int m = 0; m < 8; ++m) {
            int R = r0 + 8 * q + m;
            ob[R * NN + C]      = sL[m];
            ob[R * NN + C + NH] = sH[m];
        }
    }
}

extern "C" void kernel_launch(void* const* d_in, const int* in_sizes, int n_in,
                              void* d_out, int out_size)
{
    const float* x   = (const float*)d_in[0];
    const float* bmt = (const float*)d_in[1];
    float* out = (float*)d_out;

    const int B = in_sizes[0] / (NN * NN);   // 32
    dim3 grid(NH / TC, NH / TR, B);          // (16,16,32) = 8192 CTAs
    wav2d_kernel<<<grid, 256>>>(x, bmt, out);
}

// round 16
// speedup vs baseline: 1.1193x; 1.1193x over previous
#include <cuda_runtime.h>

#define NN 1024
#define NMASK 1023
#define NQMASK 255     // float4s per row - 1
#define NH 512
#define TC 32          // subband cols per block
#define TR 32          // subband rows per block
#define HROWS 70       // halo rows: 2*32 + 6
#define TSTRIDE 72     // intermediate row stride in floats

// lo[j] = w[7-j] (index reversal, free); hi[j] = (j odd) ? w[j] : -w[j]
// (negation folded into the FFMA operand modifier, free in SASS).
#define FMA_LO(v, j, s) (s) = fmaf((v), w[7 - (j)], (s))
#define FMA_HI(v, j, s) (s) = ((j) & 1) ? fmaf((v), w[(j)], (s)) \
                                        : fmaf((v), -w[(j)], (s))

__global__ __launch_bounds__(256, 8)
void wav2d_kernel(const float* __restrict__ x,
                  const float* __restrict__ bmt,
                  float* __restrict__ out)
{
    __shared__ float tmp[HROWS * TSTRIDE];   // 20160 B

    const int tid = threadIdx.x;
    const int b  = blockIdx.z;
    const int r0 = blockIdx.y * TR;
    const int c0 = blockIdx.x * TC;

    float w[8];
    #pragma unroll
    for (int j = 0; j < 8; ++j) w[j] = __ldg(&bmt[j]);

    const float* xb = x + (size_t)b * NN * NN;
    const int gr0 = 2 * r0 - 3;          // first halo row (wrapped per-row)
    const int gq0 = (2 * c0 - 4) >> 2;   // first halo float4 index (exact: 2c0-4 % 4 == 0)

    // ---- Phase 1: horizontal filter, global -> regs -> smem ----
    // Task t (of 70*16=1120): row = t>>4, pair = t&15 -> output cols
    // 2*pair, 2*pair+1. Loads 3 float4 with PER-FLOAT4 periodic wrap
    // ((idx)&255) — uniform path for ALL blocks, no scalar edge fallback.
    // Lanes are at 16B stride (contiguous) -> 1 wavefront per 128B.
    #pragma unroll
    for (int it = 0; it < 5; ++it) {
        int task = tid + it * 256;
        if (task < HROWS * 16) {
            int row  = task >> 4;
            int pair = task & 15;
            int gr   = (gr0 + row) & NMASK;
            const float4* rowp4 = (const float4*)(xb + (size_t)gr * NN);

            int q0 = gq0 + pair;
            float4 v0 = __ldg(rowp4 + ( q0      & NQMASK));
            float4 v1 = __ldg(rowp4 + ((q0 + 1) & NQMASK));
            float4 v2 = __ldg(rowp4 + ((q0 + 2) & NQMASK));
            float f[12] = { v0.x, v0.y, v0.z, v0.w,
                            v1.x, v1.y, v1.z, v1.w,
                            v2.x, v2.y, v2.z, v2.w };

            float sA0 = 0.f, sD0 = 0.f, sA1 = 0.f, sD1 = 0.f;
            #pragma unroll
            for (int j = 0; j < 8; ++j) {
                FMA_LO(f[1 + j], j, sA0);  FMA_HI(f[1 + j], j, sD0);
                FMA_LO(f[3 + j], j, sA1);  FMA_HI(f[3 + j], j, sD1);
            }
            *(float2*)&tmp[row * TSTRIDE + 2 * pair]      = make_float2(sA0, sA1);
            *(float2*)&tmp[row * TSTRIDE + 32 + 2 * pair] = make_float2(sD0, sD1);
        }
    }
    __syncthreads();

    // ---- Phase 2: vertical filter, warp-uniform; 8 output rows/thread ----
    // warp g: arr = g&1 (A cols [0,32) or D cols [32,64)), q = g>>1 (0..3).
    // Output rows 8q..8q+7 need tmp rows 16q..16q+21 (sliding window of 22).
    {
        const int tx  = tid & 31;
        const int g   = tid >> 5;
        const int arr = g & 1;
        const int q   = g >> 1;

        float sL[8] = {0,0,0,0,0,0,0,0};
        float sH[8] = {0,0,0,0,0,0,0,0};

        const float* col = &tmp[(16 * q) * TSTRIDE + 32 * arr + tx];
        #pragma unroll
        for (int i = 0; i < 22; ++i) {
            float v = col[i * TSTRIDE];
            #pragma unroll
            for (int m = 0; m < 8; ++m) {
                int j = i - 2 * m;
                if (j >= 0 && j < 8) {
                    FMA_LO(v, j, sL[m]);
                    FMA_HI(v, j, sH[m]);
                }
            }
        }

        // arr=0 -> top half rows; arr=1 -> bottom half (+NH).
        // Vertical low-pass -> left cols; high-pass -> right cols (+NH).
        float* ob = out + (size_t)b * NN * NN + (size_t)(arr * NH) * NN;
        const int C = c0 + tx;
        #pragma unroll
        for (int m = 0; m < 8; ++m) {
            int R = r0 + 8 * q + m;
            ob[R * NN + C]      = sL[m];
            ob[R * NN + C + NH] = sH[m];
        }
    }
}

extern "C" void kernel_launch(void* const* d_in, const int* in_sizes, int n_in,
                              void* d_out, int out_size)
{
    const float* x   = (const float*)d_in[0];
    const float* bmt = (const float*)d_in[1];
    float* out = (float*)d_out;

    const int B = in_sizes[0] / (NN * NN);   // 32
    dim3 grid(NH / TC, NH / TR, B);          // (16,16,32) = 8192 CTAs
    wav2d_kernel<<<grid, 256>>>(x, bmt, out);
}